// round 14
// baseline (speedup 1.0000x reference)
#include <cuda_runtime.h>
#include <cstdint>

// Problem constants
#define NF 8
#define NK 16
#define NY 16
#define NX 16
#define NP 32
#define NT 8
#define NB 64
#define VOL 65536          // elements per (b,f)
#define COLS 8192          // (y,x,p) columns

#define AS_STRIDE 68       // 64 cols + 4 pad (conflict-free writes / LDS.32)
#define BS_STRIDE 24       // 16 cols + 8 pad (conflict-free b-frag LDS.32)
#define AS_U32    (64*AS_STRIDE)                 // per buffer (fp32 words)
#define AS_BYTES  (2*AS_U32*4)                   // 34816 (double buffer)
#define BS_BYTES  (256*BS_STRIDE*4)              // 24576
#define SP_BYTES  (4*16*16*4)                    // 4096
#define SMEM_TOTAL (AS_BYTES + BS_BYTES + SP_BYTES)   // 63488 -> 3 CTAs/SM

// Device globals (no allocation allowed)
__device__ float g_klev[NF*NK*NP];     // klev tables (feat W build)
__device__ float g_r[NF*NK];           // geometric ratios (feat W build)
__device__ float g_klat[NF*NK*NY];     // for prep2
__device__ float g_klon[NF*NK*NX];     // for prep2
__device__ float g_ipart[NF*NK*16];    // integ partials [fk][sub]
__device__ float g_clinv[256*NF*NK];   // [sl][fk] klat*klon/(integ+1e-4)

__device__ __forceinline__ uint32_t f2tf32(float x) {
    uint32_t r; asm("cvt.rna.tf32.f32 %0, %1;" : "=r"(r) : "f"(x)); return r;
}
__device__ __forceinline__ void mma_tf32(float c[4], uint32_t a0, uint32_t a1,
                                         uint32_t a2, uint32_t a3,
                                         uint32_t b0, uint32_t b1) {
    asm volatile(
        "mma.sync.aligned.m16n8k8.row.col.f32.tf32.tf32.f32 "
        "{%0,%1,%2,%3},{%4,%5,%6,%7},{%8,%9},{%0,%1,%2,%3};"
        : "+f"(c[0]), "+f"(c[1]), "+f"(c[2]), "+f"(c[3])
        : "r"(a0), "r"(a1), "r"(a2), "r"(a3), "r"(b0), "r"(b1));
}

// cp.async helpers (16B, default .ca path)
__device__ __forceinline__ void cp16(void* dst_smem, const void* src) {
    uint32_t d = (uint32_t)__cvta_generic_to_shared(dst_smem);
    asm volatile("cp.async.ca.shared.global [%0],[%1],16;" :: "r"(d), "l"(src));
}
__device__ __forceinline__ void cp_commit() {
    asm volatile("cp.async.commit_group;");
}
template<int N> __device__ __forceinline__ void cp_wait() {
    asm volatile("cp.async.wait_group %0;" :: "n"(N));
}

__device__ __forceinline__ int bitrev4(int l) {
    return ((l & 1) << 3) | ((l & 2) << 1) | ((l & 4) >> 1) | ((l & 8) >> 3);
}

// ---------------------------------------------------------------------------
// prep1: grid 128 = (f, sub). Builds 1D tables for all 16 k of f in smem
// (sub 0 publishes them to globals), integrates its 1/16 of the quadrature
// grid for ALL 16 k simultaneously (qw traffic 2 MB total vs 32 MB before),
// writes non-atomic partials, zeroes the output buffer.
// ---------------------------------------------------------------------------
__global__ __launch_bounds__(256)
void prep1_kernel(const float* __restrict__ qw,
                  const float* __restrict__ mu_lat, const float* __restrict__ ls_lat,
                  const float* __restrict__ mu_lon, const float* __restrict__ ls_lon,
                  const float* __restrict__ mu_lev, const float* __restrict__ ls_lev,
                  const float* __restrict__ lt_time,
                  float* __restrict__ out)
{
    __shared__ float s_lat[16][16], s_lon[16][16], s_lev[16][32], s_r[16];
    __shared__ float s_ired[8*16];

    const int bid = blockIdx.x;
    const int f   = bid >> 4;
    const int sub = bid & 15;
    const int tid = threadIdx.x;
    const int lane = tid & 31, wid = tid >> 5;

    // Zero out: 128 CTAs x 64 = 8192
    if (tid < 64) out[bid*64 + tid] = 0.f;

    // Table build: k = tid>>4, i = tid&15
    {
        const int k = tid >> 4, i = tid & 15;
        const int fk = f*16 + k;
        {   // klat
            const float c = -1.f + 2.f * (float)i / 15.f;
            const float z = (c - mu_lat[fk]) / expf(ls_lat[fk]);
            const float v = expf(-0.5f * z * z);
            s_lat[k][i] = v;
            if (sub == 0) g_klat[fk*16 + i] = v;
        }
        {   // klon
            const float c = -1.f + 2.f * (float)i / 15.f;
            const float z = (c - mu_lon[fk]) / expf(ls_lon[fk]);
            const float v = expf(-0.5f * z * z);
            s_lon[k][i] = v;
            if (sub == 0) g_klon[fk*16 + i] = v;
        }
        {   // klev (two halves)
            const float mu = mu_lev[fk];
            const float si = expf(ls_lev[fk]);
            #pragma unroll
            for (int h = 0; h < 2; ++h) {
                const int p = i + h*16;
                const float c = -1.f + 2.f * (float)p / 31.f;
                const float z = (c - mu) / si;
                const float v = expf(-0.5f * z * z);
                s_lev[k][p] = v;
                if (sub == 0) g_klev[fk*32 + p] = v;
            }
        }
        if (tid < 16) {
            const float r = expf(-1.f / (expf(lt_time[f*16 + tid]) + 1e-6f));
            s_r[tid] = r;
            if (sub == 0) g_r[f*16 + tid] = r;
        }
    }
    __syncthreads();

    // Integrate 512 columns (2 per thread) for all 16 k
    float wf[16];
    #pragma unroll
    for (int k = 0; k < 16; ++k) wf[k] = 0.f;
    const float4* q4 = (const float4*)qw;
    #pragma unroll
    for (int it = 0; it < 2; ++it) {
        const int col = sub*512 + it*256 + tid;
        const float4 q0 = q4[col*2];
        const float4 q1 = q4[col*2 + 1];
        const int p = col & 31, x = (col >> 5) & 15, y = col >> 9;
        #pragma unroll
        for (int k = 0; k < 16; ++k) {
            const float r = s_r[k];
            float s = q1.w;
            s = fmaf(s, r, q1.z); s = fmaf(s, r, q1.y); s = fmaf(s, r, q1.x);
            s = fmaf(s, r, q0.w); s = fmaf(s, r, q0.z); s = fmaf(s, r, q0.y);
            s = fmaf(s, r, q0.x);
            wf[k] = fmaf(s, s_lat[k][y] * s_lon[k][x] * s_lev[k][p], wf[k]);
        }
    }

    // Reduce 16 values over 256 threads (halving transpose, R13-proven)
    #pragma unroll
    for (int s = 0; s < 4; ++s) {
        const int stride = 1 << s;
        const int nh = 8 >> s;
        const bool hi = (lane >> s) & 1;
        #pragma unroll
        for (int i = 0; i < nh; ++i) {
            float send = hi ? wf[i] : wf[i + nh];
            float keep = hi ? wf[i + nh] : wf[i];
            wf[i] = keep + __shfl_xor_sync(0xffffffffu, send, stride);
        }
    }
    wf[0] += __shfl_xor_sync(0xffffffffu, wf[0], 16);
    if (lane < 16) s_ired[wid*16 + bitrev4(lane)] = wf[0];
    __syncthreads();
    if (tid < 16) {
        float s = 0.f;
        #pragma unroll
        for (int w8 = 0; w8 < 8; ++w8) s += s_ired[w8*16 + tid];
        g_ipart[(f*16 + tid)*16 + sub] = s;
    }
}

// ---------------------------------------------------------------------------
// prep2: grid 32, CTA covers 8 sl values. Materializes
// g_clinv[sl][fk] = klat[fk][y]*klon[fk][x] / (integ[fk] + 1e-4).
// ---------------------------------------------------------------------------
__global__ __launch_bounds__(256)
void prep2_kernel()
{
    __shared__ float s_ip[2048];      // g_ipart staged
    __shared__ float s_kla[2048];     // g_klat staged
    __shared__ float s_klo[2048];     // g_klon staged
    __shared__ float s_rinv[128];

    const int bid = blockIdx.x;
    const int tid = threadIdx.x;

    #pragma unroll
    for (int j = 0; j < 8; ++j) {
        const int idx = j*256 + tid;
        s_ip[idx]  = g_ipart[idx];
        s_kla[idx] = g_klat[idx];
        s_klo[idx] = g_klon[idx];
    }
    __syncthreads();
    if (tid < 128) {
        float s = 0.f;
        #pragma unroll
        for (int i = 0; i < 16; ++i) s += s_ip[tid*16 + i];
        s_rinv[tid] = 1.f / (s + 1e-4f);
    }
    __syncthreads();

    #pragma unroll
    for (int j = 0; j < 4; ++j) {
        const int o = j*256 + tid;            // 0..1023
        const int sl = bid*8 + (o >> 7);
        const int fk = o & 127;
        const int y = sl >> 4, x = sl & 15;
        g_clinv[sl*128 + fk] = s_kla[fk*16 + y] * s_klo[fk*16 + x] * s_rinv[fk];
    }
}

// ---------------------------------------------------------------------------
// Main GEMM kernel (R12 structure): grid = 2048 (f = bid&7, sl = bid>>3).
// C[64,16] = patch[64, 256] x W[256, 16] (tf32 mma.sync m16n8k8).
// cp.async double buffer, commit-per-stage, wait_group<1> + CTA barrier.
// s_cl now ONE coalesced load from g_clinv (normalization prebaked).
// Epilogue: pair-reduce K-halves via smem, atomicAdd into out.
// ---------------------------------------------------------------------------
__global__ __launch_bounds__(256, 3)
void feat_kernel(const float* __restrict__ patch, const float* __restrict__ qw,
                 float* __restrict__ out)
{
    extern __shared__ __align__(16) char dynsmem[];
    float*    As    = (float*)dynsmem;                         // [2][64][68] fp32
    uint32_t* Bs    = (uint32_t*)(dynsmem + AS_BYTES);         // [256][24] tf32
    float*    s_par = (float*)(dynsmem + AS_BYTES + BS_BYTES); // [4][16][16]
    __shared__ float s_cl[16];

    const int bid  = blockIdx.x;
    const int f    = bid & 7;
    const int sl   = bid >> 3;            // yx index 0..255
    const int tid  = threadIdx.x;
    const int lane = tid & 31, wid = tid >> 5;
    const int g = lane >> 2, tg = lane & 3;
    const int mt = wid & 3, kh = wid >> 2;

    const size_t bstride = (size_t)NF * VOL;
    const float* abase = patch + (size_t)f * VOL + (size_t)sl * 256;
    const int row0 = tid >> 4;            // rows row0, +16, +32, +48
    const int c4   = tid & 15;

    // Kick off stage 0 copies immediately (overlap with table build)
    #pragma unroll
    for (int it = 0; it < 4; ++it)
        cp16(&As[(row0 + it*16)*AS_STRIDE + c4*4],
             abase + (size_t)(row0 + it*16) * bstride + c4*4);
    cp_commit();

    if (tid < 16) s_cl[tid] = g_clinv[sl*128 + f*16 + tid];
    __syncthreads();

    // Build B: W[i][k] = qw_i * klev*r^t * clinv, tf32
    {
        const int p = (tid >> 3) & 31, t = tid & 7;
        const float qwv = qw[sl*256 + tid];
        #pragma unroll
        for (int kq = 0; kq < 4; ++kq) {
            uint4 pk;
            uint32_t* pe = (uint32_t*)&pk;
            #pragma unroll
            for (int e = 0; e < 4; ++e) {
                const int k = kq*4 + e;
                const float r = g_r[f*16 + k];
                const float r2 = r*r, r4 = r2*r2;
                float rt = 1.f;
                if (t & 1) rt *= r;
                if (t & 2) rt *= r2;
                if (t & 4) rt *= r4;
                const float kl = g_klev[(f*16 + k)*NP + p];
                pe[e] = f2tf32(qwv * kl * rt * s_cl[k]);
            }
            *(uint4*)&Bs[tid*BS_STRIDE + kq*4] = pk;
        }
    }

    // Stage 1 copies into buffer 1
    #pragma unroll
    for (int it = 0; it < 4; ++it)
        cp16(&As[AS_U32 + (row0 + it*16)*AS_STRIDE + c4*4],
             abase + (size_t)(row0 + it*16) * bstride + 64 + c4*4);
    cp_commit();

    float acc[2][4] = {};
    #pragma unroll
    for (int sub = 0; sub < 4; ++sub) {
        if (sub < 3) cp_wait<1>(); else cp_wait<0>();
        __syncthreads();

        const float* Ab = As + (sub & 1)*AS_U32;
        const float* ar0 = Ab + (mt*16 + g    )*AS_STRIDE;
        const float* ar8 = Ab + (mt*16 + g + 8)*AS_STRIDE;
        #pragma unroll
        for (int j = 0; j < 4; ++j) {
            const int icl = kh*32 + j*8;       // col within 64-col round
            const int icb = sub*64 + icl;      // row in Bs (0..255)
            const uint32_t a0 = f2tf32(ar0[icl + tg]);
            const uint32_t a1 = f2tf32(ar8[icl + tg]);
            const uint32_t a2 = f2tf32(ar0[icl + tg + 4]);
            const uint32_t a3 = f2tf32(ar8[icl + tg + 4]);
            const uint32_t b0 = Bs[(icb + tg    )*BS_STRIDE + g];
            const uint32_t b1 = Bs[(icb + tg + 4)*BS_STRIDE + g];
            const uint32_t c0 = Bs[(icb + tg    )*BS_STRIDE + g + 8];
            const uint32_t c1 = Bs[(icb + tg + 4)*BS_STRIDE + g + 8];
            mma_tf32(acc[0], a0, a1, a2, a3, b0, b1);
            mma_tf32(acc[1], a0, a1, a2, a3, c0, c1);
        }
        __syncthreads();   // buffer sub&1 fully consumed

        if (sub < 2) {
            const int col0 = (sub + 2)*64;
            #pragma unroll
            for (int it = 0; it < 4; ++it)
                cp16(&As[(sub & 1)*AS_U32 + (row0 + it*16)*AS_STRIDE + c4*4],
                     abase + (size_t)(row0 + it*16) * bstride + col0 + c4*4);
            cp_commit();
        }
    }

    // Pair-reduce the two K-halves, then atomicAdd into out.
    if (kh == 1) {
        float* sp = s_par + mt*256;
        sp[(g    )*16 + tg*2    ] = acc[0][0];
        sp[(g    )*16 + tg*2 + 1] = acc[0][1];
        sp[(g + 8)*16 + tg*2    ] = acc[0][2];
        sp[(g + 8)*16 + tg*2 + 1] = acc[0][3];
        sp[(g    )*16 + 8 + tg*2    ] = acc[1][0];
        sp[(g    )*16 + 8 + tg*2 + 1] = acc[1][1];
        sp[(g + 8)*16 + 8 + tg*2    ] = acc[1][2];
        sp[(g + 8)*16 + 8 + tg*2 + 1] = acc[1][3];
    }
    __syncthreads();
    if (kh == 0) {
        const float* sp = s_par + mt*256;
        const int r0 = mt*16 + g, r1 = r0 + 8;
        float* o0 = out + (size_t)r0 * (NF*NK) + f*NK;
        float* o1 = out + (size_t)r1 * (NF*NK) + f*NK;
        atomicAdd(&o0[tg*2    ], acc[0][0] + sp[(g    )*16 + tg*2    ]);
        atomicAdd(&o0[tg*2 + 1], acc[0][1] + sp[(g    )*16 + tg*2 + 1]);
        atomicAdd(&o1[tg*2    ], acc[0][2] + sp[(g + 8)*16 + tg*2    ]);
        atomicAdd(&o1[tg*2 + 1], acc[0][3] + sp[(g + 8)*16 + tg*2 + 1]);
        atomicAdd(&o0[8 + tg*2    ], acc[1][0] + sp[(g    )*16 + 8 + tg*2    ]);
        atomicAdd(&o0[8 + tg*2 + 1], acc[1][1] + sp[(g    )*16 + 8 + tg*2 + 1]);
        atomicAdd(&o1[8 + tg*2    ], acc[1][2] + sp[(g + 8)*16 + 8 + tg*2    ]);
        atomicAdd(&o1[8 + tg*2 + 1], acc[1][3] + sp[(g + 8)*16 + 8 + tg*2 + 1]);
    }
}

// ---------------------------------------------------------------------------
// Launch. Inputs (metadata order): patch, quadweights, mu_lat, logsigma_lat,
// mu_lon, logsigma_lon, mu_lev, logsigma_lev, logtau_time.
// ---------------------------------------------------------------------------
extern "C" void kernel_launch(void* const* d_in, const int* in_sizes, int n_in,
                              void* d_out, int out_size)
{
    (void)in_sizes; (void)n_in; (void)out_size;
    const float* patch  = (const float*)d_in[0];
    const float* qw     = (const float*)d_in[1];
    const float* mu_lat = (const float*)d_in[2];
    const float* ls_lat = (const float*)d_in[3];
    const float* mu_lon = (const float*)d_in[4];
    const float* ls_lon = (const float*)d_in[5];
    const float* mu_lev = (const float*)d_in[6];
    const float* ls_lev = (const float*)d_in[7];
    const float* lt     = (const float*)d_in[8];
    float* out = (float*)d_out;

    static bool attr_set = false;
    if (!attr_set) {
        cudaFuncSetAttribute(feat_kernel,
                             cudaFuncAttributeMaxDynamicSharedMemorySize, SMEM_TOTAL);
        attr_set = true;
    }

    prep1_kernel<<<128, 256>>>(qw, mu_lat, ls_lat, mu_lon, ls_lon,
                               mu_lev, ls_lev, lt, out);
    prep2_kernel<<<32, 256>>>();
    feat_kernel<<<2048, 256, SMEM_TOTAL>>>(patch, qw, out);
}

// round 15
// speedup vs baseline: 1.2317x; 1.2317x over previous
#include <cuda_runtime.h>
#include <cstdint>

// Problem constants
#define NF 8
#define NK 16
#define NY 16
#define NX 16
#define NP 32
#define NT 8
#define NB 64
#define VOL 65536          // elements per (b,f)

#define AS_STRIDE 68       // 64 cols + 4 pad (conflict-free writes / LDS.32)
#define BT_STRIDE 260      // 256 cols + 4 pad (banks 4g+tg: conflict-free)
#define AS_U32    (64*AS_STRIDE)                 // per buffer (fp32 words)
#define AS_BYTES  (2*AS_U32*4)                   // 34816 (double buffer)
#define BT_BYTES  (16*BT_STRIDE*4)               // 16640
#define SMEM_TOTAL (AS_BYTES + BT_BYTES)         // 51456 -> 4 CTAs/SM

// Device globals (no allocation allowed)
__device__ float g_klev[NF*NK*NP];     // klev tables (feat W build)
__device__ float g_r[NF*NK];           // geometric ratios (feat W build)
__device__ float g_klat[NF*NK*NY];
__device__ float g_klon[NF*NK*NX];
__device__ float g_ipart[NF*NK*16];    // integ partials [fk][sub] (= [bid])

__device__ __forceinline__ uint32_t f2tf32(float x) {
    uint32_t r; asm("cvt.rna.tf32.f32 %0, %1;" : "=r"(r) : "f"(x)); return r;
}
__device__ __forceinline__ void mma_tf32(float c[4], uint32_t a0, uint32_t a1,
                                         uint32_t a2, uint32_t a3,
                                         uint32_t b0, uint32_t b1) {
    asm volatile(
        "mma.sync.aligned.m16n8k8.row.col.f32.tf32.tf32.f32 "
        "{%0,%1,%2,%3},{%4,%5,%6,%7},{%8,%9},{%0,%1,%2,%3};"
        : "+f"(c[0]), "+f"(c[1]), "+f"(c[2]), "+f"(c[3])
        : "r"(a0), "r"(a1), "r"(a2), "r"(a3), "r"(b0), "r"(b1));
}

// cp.async helpers (16B, default .ca path)
__device__ __forceinline__ void cp16(void* dst_smem, const void* src) {
    uint32_t d = (uint32_t)__cvta_generic_to_shared(dst_smem);
    asm volatile("cp.async.ca.shared.global [%0],[%1],16;" :: "r"(d), "l"(src));
}
__device__ __forceinline__ void cp_commit() {
    asm volatile("cp.async.commit_group;");
}
template<int N> __device__ __forceinline__ void cp_wait() {
    asm volatile("cp.async.wait_group %0;" :: "n"(N));
}

// ---------------------------------------------------------------------------
// prep: grid 2048 = (fk = bid>>4, sub = bid&15). Flat single-phase kernel:
// each thread integrates 2 columns (fused single-expf Gaussian product +
// Horner over t), 5-shfl + smem reduce, non-atomic partial to g_ipart[bid].
// sub==0 CTAs also publish the 1D tables; zeroes the output buffer.
// ---------------------------------------------------------------------------
__global__ __launch_bounds__(256)
void prep_kernel(const float* __restrict__ qw,
                 const float* __restrict__ mu_lat, const float* __restrict__ ls_lat,
                 const float* __restrict__ mu_lon, const float* __restrict__ ls_lon,
                 const float* __restrict__ mu_lev, const float* __restrict__ ls_lev,
                 const float* __restrict__ lt_time,
                 float* __restrict__ out)
{
    __shared__ float s_part[8];

    const int bid = blockIdx.x;
    const int fk  = bid >> 4;
    const int sub = bid & 15;
    const int tid = threadIdx.x;

    // Zero out: 2048 CTAs x 4 = 8192
    if (tid < 4) out[bid*4 + tid] = 0.f;

    // Broadcast parameter loads (L2-hot after first CTAs)
    const float mla = mu_lat[fk], sla = expf(ls_lat[fk]);
    const float mlo = mu_lon[fk], slo = expf(ls_lon[fk]);
    const float mle = mu_lev[fk], sle = expf(ls_lev[fk]);
    const float r   = expf(-1.f / (expf(lt_time[fk]) + 1e-6f));

    // Tables (sub 0 only): matches reference _gaussian1d / _exponential1d
    if (sub == 0) {
        if (tid < 16) {
            const float c = -1.f + 2.f * (float)tid / 15.f;
            const float zy = (c - mla) / sla;
            g_klat[fk*16 + tid] = expf(-0.5f * zy * zy);
            const float zx = (c - mlo) / slo;
            g_klon[fk*16 + tid] = expf(-0.5f * zx * zx);
        } else if (tid < 48) {
            const int p = tid - 16;
            const float c = -1.f + 2.f * (float)p / 31.f;
            const float z = (c - mle) / sle;
            g_klev[fk*32 + p] = expf(-0.5f * z * z);
        }
        if (tid == 0) g_r[fk] = r;
    }

    // Integrate 2 columns per thread
    const float4* q4 = (const float4*)qw;
    float local = 0.f;
    #pragma unroll
    for (int it = 0; it < 2; ++it) {
        const int col = sub*512 + it*256 + tid;
        const float4 q0 = q4[col*2];
        const float4 q1 = q4[col*2 + 1];
        float s = q1.w;
        s = fmaf(s, r, q1.z); s = fmaf(s, r, q1.y); s = fmaf(s, r, q1.x);
        s = fmaf(s, r, q0.w); s = fmaf(s, r, q0.z); s = fmaf(s, r, q0.y);
        s = fmaf(s, r, q0.x);
        const int p = col & 31, x = (col >> 5) & 15, y = col >> 9;
        const float zy = (-1.f + 2.f * (float)y / 15.f - mla) / sla;
        const float zx = (-1.f + 2.f * (float)x / 15.f - mlo) / slo;
        const float zp = (-1.f + 2.f * (float)p / 31.f - mle) / sle;
        local += s * expf(-0.5f * (zy*zy + zx*zx + zp*zp));
    }
    #pragma unroll
    for (int o = 16; o; o >>= 1) local += __shfl_xor_sync(0xffffffffu, local, o);
    if ((tid & 31) == 0) s_part[tid >> 5] = local;
    __syncthreads();
    if (tid == 0) {
        float s = 0.f;
        #pragma unroll
        for (int w = 0; w < 8; ++w) s += s_part[w];
        g_ipart[bid] = s;
    }
}

// ---------------------------------------------------------------------------
// Main GEMM kernel (R12 mainloop): grid = 2048 (f = bid&7, sl = bid>>3).
// C[64,16] = patch[64, 256] x W[256, 16] (tf32 mma.sync m16n8k8).
// cp.async double buffer, commit-per-stage, wait_group<1> + CTA barrier.
// B stored TRANSPOSED Bt[16][260] (16.6 KB; banks 4g+tg conflict-free) and
// s_par aliases As buffer 0 -> 51.5 KB total smem -> 4 CTAs/SM with the
// kernel's natural 63 registers (no codegen squeeze).
// Epilogue: pair-reduce K-halves via smem, atomicAdd into out.
// ---------------------------------------------------------------------------
__global__ __launch_bounds__(256, 4)
void feat_kernel(const float* __restrict__ patch, const float* __restrict__ qw,
                 float* __restrict__ out)
{
    extern __shared__ __align__(16) char dynsmem[];
    float*    As    = (float*)dynsmem;                         // [2][64][68] fp32
    uint32_t* Bt    = (uint32_t*)(dynsmem + AS_BYTES);         // [16][260] tf32
    float*    s_par = (float*)dynsmem;                         // alias As buf0
    __shared__ float s_cl[16];

    const int bid  = blockIdx.x;
    const int f    = bid & 7;
    const int sl   = bid >> 3;            // yx index 0..255
    const int tid  = threadIdx.x;
    const int lane = tid & 31, wid = tid >> 5;
    const int g = lane >> 2, tg = lane & 3;
    const int mt = wid & 3, kh = wid >> 2;

    const size_t bstride = (size_t)NF * VOL;
    const float* abase = patch + (size_t)f * VOL + (size_t)sl * 256;
    const int row0 = tid >> 4;            // rows row0, +16, +32, +48
    const int c4   = tid & 15;

    // Kick off stage 0 copies immediately (overlap with table fetch)
    #pragma unroll
    for (int it = 0; it < 4; ++it)
        cp16(&As[(row0 + it*16)*AS_STRIDE + c4*4],
             abase + (size_t)(row0 + it*16) * bstride + c4*4);
    cp_commit();

    if (tid < 16) {
        const int fk = f*16 + tid;
        const float4* ip = (const float4*)&g_ipart[fk*16];
        float4 a = ip[0], b = ip[1], c = ip[2], d = ip[3];
        float integ = ((a.x + a.y) + (a.z + a.w)) + ((b.x + b.y) + (b.z + b.w))
                    + ((c.x + c.y) + (c.z + c.w)) + ((d.x + d.y) + (d.z + d.w));
        s_cl[tid] = g_klat[fk*16 + (sl >> 4)] * g_klon[fk*16 + (sl & 15)]
                    / (integ + 1e-4f);
    }
    __syncthreads();

    // Build Bt (transposed): W[i=tid][k] = qw_i * klev*r^t * clinv, tf32
    {
        const int p = (tid >> 3) & 31, t = tid & 7;
        const float qwv = qw[sl*256 + tid];
        #pragma unroll
        for (int k = 0; k < 16; ++k) {
            const float r = g_r[f*16 + k];
            const float r2 = r*r, r4 = r2*r2;
            float rt = 1.f;
            if (t & 1) rt *= r;
            if (t & 2) rt *= r2;
            if (t & 4) rt *= r4;
            const float kl = g_klev[(f*16 + k)*NP + p];
            Bt[k*BT_STRIDE + tid] = f2tf32(qwv * kl * rt * s_cl[k]);
        }
    }

    // Stage 1 copies into buffer 1
    #pragma unroll
    for (int it = 0; it < 4; ++it)
        cp16(&As[AS_U32 + (row0 + it*16)*AS_STRIDE + c4*4],
             abase + (size_t)(row0 + it*16) * bstride + 64 + c4*4);
    cp_commit();

    float acc[2][4] = {};
    #pragma unroll
    for (int sub = 0; sub < 4; ++sub) {
        if (sub < 3) cp_wait<1>(); else cp_wait<0>();
        __syncthreads();

        const float* Ab = As + (sub & 1)*AS_U32;
        const float* ar0 = Ab + (mt*16 + g    )*AS_STRIDE;
        const float* ar8 = Ab + (mt*16 + g + 8)*AS_STRIDE;
        #pragma unroll
        for (int j = 0; j < 4; ++j) {
            const int icl = kh*32 + j*8;       // col within 64-col round
            const int icb = sub*64 + icl;      // col in Bt (0..255)
            const uint32_t a0 = f2tf32(ar0[icl + tg]);
            const uint32_t a1 = f2tf32(ar8[icl + tg]);
            const uint32_t a2 = f2tf32(ar0[icl + tg + 4]);
            const uint32_t a3 = f2tf32(ar8[icl + tg + 4]);
            const uint32_t b0 = Bt[(g    )*BT_STRIDE + icb + tg];
            const uint32_t b1 = Bt[(g    )*BT_STRIDE + icb + tg + 4];
            const uint32_t c0 = Bt[(g + 8)*BT_STRIDE + icb + tg];
            const uint32_t c1 = Bt[(g + 8)*BT_STRIDE + icb + tg + 4];
            mma_tf32(acc[0], a0, a1, a2, a3, b0, b1);
            mma_tf32(acc[1], a0, a1, a2, a3, c0, c1);
        }
        __syncthreads();   // buffer sub&1 fully consumed

        if (sub < 2) {
            const int col0 = (sub + 2)*64;
            #pragma unroll
            for (int it = 0; it < 4; ++it)
                cp16(&As[(sub & 1)*AS_U32 + (row0 + it*16)*AS_STRIDE + c4*4],
                     abase + (size_t)(row0 + it*16) * bstride + col0 + c4*4);
            cp_commit();
        }
    }

    // Pair-reduce the two K-halves (s_par aliases As buf0 — dead after the
    // final mainloop barrier), then atomicAdd into out.
    if (kh == 1) {
        float* sp = s_par + mt*256;
        sp[(g    )*16 + tg*2    ] = acc[0][0];
        sp[(g    )*16 + tg*2 + 1] = acc[0][1];
        sp[(g + 8)*16 + tg*2    ] = acc[0][2];
        sp[(g + 8)*16 + tg*2 + 1] = acc[0][3];
        sp[(g    )*16 + 8 + tg*2    ] = acc[1][0];
        sp[(g    )*16 + 8 + tg*2 + 1] = acc[1][1];
        sp[(g + 8)*16 + 8 + tg*2    ] = acc[1][2];
        sp[(g + 8)*16 + 8 + tg*2 + 1] = acc[1][3];
    }
    __syncthreads();
    if (kh == 0) {
        const float* sp = s_par + mt*256;
        const int r0 = mt*16 + g, r1 = r0 + 8;
        float* o0 = out + (size_t)r0 * (NF*NK) + f*NK;
        float* o1 = out + (size_t)r1 * (NF*NK) + f*NK;
        atomicAdd(&o0[tg*2    ], acc[0][0] + sp[(g    )*16 + tg*2    ]);
        atomicAdd(&o0[tg*2 + 1], acc[0][1] + sp[(g    )*16 + tg*2 + 1]);
        atomicAdd(&o1[tg*2    ], acc[0][2] + sp[(g + 8)*16 + tg*2    ]);
        atomicAdd(&o1[tg*2 + 1], acc[0][3] + sp[(g + 8)*16 + tg*2 + 1]);
        atomicAdd(&o0[8 + tg*2    ], acc[1][0] + sp[(g    )*16 + 8 + tg*2    ]);
        atomicAdd(&o0[8 + tg*2 + 1], acc[1][1] + sp[(g    )*16 + 8 + tg*2 + 1]);
        atomicAdd(&o1[8 + tg*2    ], acc[1][2] + sp[(g + 8)*16 + 8 + tg*2    ]);
        atomicAdd(&o1[8 + tg*2 + 1], acc[1][3] + sp[(g + 8)*16 + 8 + tg*2 + 1]);
    }
}

// ---------------------------------------------------------------------------
// Launch. Inputs (metadata order): patch, quadweights, mu_lat, logsigma_lat,
// mu_lon, logsigma_lon, mu_lev, logsigma_lev, logtau_time.
// ---------------------------------------------------------------------------
extern "C" void kernel_launch(void* const* d_in, const int* in_sizes, int n_in,
                              void* d_out, int out_size)
{
    (void)in_sizes; (void)n_in; (void)out_size;
    const float* patch  = (const float*)d_in[0];
    const float* qw     = (const float*)d_in[1];
    const float* mu_lat = (const float*)d_in[2];
    const float* ls_lat = (const float*)d_in[3];
    const float* mu_lon = (const float*)d_in[4];
    const float* ls_lon = (const float*)d_in[5];
    const float* mu_lev = (const float*)d_in[6];
    const float* ls_lev = (const float*)d_in[7];
    const float* lt     = (const float*)d_in[8];
    float* out = (float*)d_out;

    static bool attr_set = false;
    if (!attr_set) {
        cudaFuncSetAttribute(feat_kernel,
                             cudaFuncAttributeMaxDynamicSharedMemorySize, SMEM_TOTAL);
        attr_set = true;
    }

    prep_kernel<<<2048, 256>>>(qw, mu_lat, ls_lat, mu_lon, ls_lon,
                               mu_lev, ls_lev, lt, out);
    feat_kernel<<<2048, 256, SMEM_TOTAL>>>(patch, qw, out);
}

// round 16
// speedup vs baseline: 1.2897x; 1.0471x over previous
#include <cuda_runtime.h>
#include <cstdint>

// Problem constants
#define NF 8
#define NK 16
#define NY 16
#define NX 16
#define NP 32
#define NT 8
#define NB 64
#define VOL 65536          // elements per (b,f)

#define AS_STRIDE 68       // 64 cols + 4 pad (conflict-free writes / LDS.32)
#define BS_STRIDE 24       // 16 cols + 8 pad (conflict-free b-frag LDS.32)
#define AS_U32    (64*AS_STRIDE)                 // per buffer (fp32 words)
#define AS_BYTES  (2*AS_U32*4)                   // 34816 (double buffer)
#define BS_BYTES  (256*BS_STRIDE*4)              // 24576
#define SP_BYTES  (4*16*16*4)                    // 4096
#define SMEM_TOTAL (AS_BYTES + BS_BYTES + SP_BYTES)   // 63488 -> 3 CTAs/SM

#define NCTA  2048
#define NPROD 128

// Device globals (no allocation allowed; zero at load, reset each launch)
__device__ float        g_klev[NF*NK*NP];
__device__ float        g_r[NF*NK];
__device__ float        g_klat[NF*NK*NY];
__device__ float        g_klon[NF*NK*NX];
__device__ float        g_ipart[NF*NK*16];   // [fk][slp]
__device__ unsigned int g_done;              // producer completion counter
__device__ unsigned int g_fin;               // CTA completion counter

__device__ __forceinline__ uint32_t f2tf32(float x) {
    uint32_t r; asm("cvt.rna.tf32.f32 %0, %1;" : "=r"(r) : "f"(x)); return r;
}
__device__ __forceinline__ void mma_tf32(float c[4], uint32_t a0, uint32_t a1,
                                         uint32_t a2, uint32_t a3,
                                         uint32_t b0, uint32_t b1) {
    asm volatile(
        "mma.sync.aligned.m16n8k8.row.col.f32.tf32.tf32.f32 "
        "{%0,%1,%2,%3},{%4,%5,%6,%7},{%8,%9},{%0,%1,%2,%3};"
        : "+f"(c[0]), "+f"(c[1]), "+f"(c[2]), "+f"(c[3])
        : "r"(a0), "r"(a1), "r"(a2), "r"(a3), "r"(b0), "r"(b1));
}

// cp.async helpers (16B, default .ca path)
__device__ __forceinline__ void cp16(void* dst_smem, const void* src) {
    uint32_t d = (uint32_t)__cvta_generic_to_shared(dst_smem);
    asm volatile("cp.async.ca.shared.global [%0],[%1],16;" :: "r"(d), "l"(src));
}
__device__ __forceinline__ void cp_commit() {
    asm volatile("cp.async.commit_group;");
}
template<int N> __device__ __forceinline__ void cp_wait() {
    asm volatile("cp.async.wait_group %0;" :: "n"(N));
}

__device__ __forceinline__ int bitrev4(int l) {
    return ((l & 1) << 3) | ((l & 2) << 1) | ((l & 4) >> 1) | ((l & 8) >> 3);
}

// ---------------------------------------------------------------------------
// Single fused kernel. grid = 2048 (f = bid&7, sl = bid>>3 = one yx slice).
// CTAs bid<128 are ALSO producers: tables + integration partials for (f, slp)
// hidden under their cp.async prologue; a g_done gate releases everyone.
// Then: byte-identical R12 tf32 GEMM (cp.async double buffer, 3 CTAs/SM).
// ---------------------------------------------------------------------------
__global__ __launch_bounds__(256, 3)
void feat_kernel(const float* __restrict__ patch, const float* __restrict__ qw,
                 const float* __restrict__ mu_lat, const float* __restrict__ ls_lat,
                 const float* __restrict__ mu_lon, const float* __restrict__ ls_lon,
                 const float* __restrict__ mu_lev, const float* __restrict__ ls_lev,
                 const float* __restrict__ lt_time,
                 float* __restrict__ out)
{
    extern __shared__ __align__(16) char dynsmem[];
    float*    As    = (float*)dynsmem;                         // [2][64][68] fp32
    uint32_t* Bs    = (uint32_t*)(dynsmem + AS_BYTES);         // [256][24] tf32
    float*    s_par = (float*)(dynsmem + AS_BYTES + BS_BYTES); // [4][16][16]
    __shared__ float s_cl[16];
    __shared__ float s_r[16];

    const int bid  = blockIdx.x;
    const int f    = bid & 7;
    const int sl   = bid >> 3;            // yx index 0..255
    const int tid  = threadIdx.x;
    const int lane = tid & 31, wid = tid >> 5;
    const int g = lane >> 2, tg = lane & 3;
    const int mt = wid & 3, kh = wid >> 2;

    const size_t bstride = (size_t)NF * VOL;
    const float* abase = patch + (size_t)f * VOL + (size_t)sl * 256;
    const int row0 = tid >> 4;            // rows row0, +16, +32, +48
    const int c4   = tid & 15;

    // Stage 0 + stage 1 cp.async immediately (independent of tables)
    #pragma unroll
    for (int it = 0; it < 4; ++it)
        cp16(&As[(row0 + it*16)*AS_STRIDE + c4*4],
             abase + (size_t)(row0 + it*16) * bstride + c4*4);
    cp_commit();
    #pragma unroll
    for (int it = 0; it < 4; ++it)
        cp16(&As[AS_U32 + (row0 + it*16)*AS_STRIDE + c4*4],
             abase + (size_t)(row0 + it*16) * bstride + 64 + c4*4);
    cp_commit();

    // ---- Producer role: bid < 128 -> (f = bid&7, slp = bid>>3) ----
    if (bid < NPROD) {
        const int slp = sl;               // 0..15 strip index
        float* s_lat = s_par;             // [16][16]
        float* s_lon = s_par + 256;       // [16][16]
        float* s_lev = s_par + 512;       // [16][32]
        float* s_ired = (float*)Bs;       // 128 floats, Bs region free pre-gate

        {   // table build: k = tid>>4, i = tid&15
            const int k = tid >> 4, i = tid & 15;
            const int fk = f*16 + k;
            const float c = -1.f + 2.f * (float)i / 15.f;
            const float zy = (c - mu_lat[fk]) / expf(ls_lat[fk]);
            const float vy = expf(-0.5f * zy * zy);
            s_lat[k*16 + i] = vy;
            const float zx = (c - mu_lon[fk]) / expf(ls_lon[fk]);
            const float vx = expf(-0.5f * zx * zx);
            s_lon[k*16 + i] = vx;
            const float mle = mu_lev[fk], sle = expf(ls_lev[fk]);
            float vp0, vp1;
            {
                const float cp0 = -1.f + 2.f * (float)i / 31.f;
                const float zp = (cp0 - mle) / sle;
                vp0 = expf(-0.5f * zp * zp);
                s_lev[k*32 + i] = vp0;
                const float cp1 = -1.f + 2.f * (float)(i + 16) / 31.f;
                const float zq = (cp1 - mle) / sle;
                vp1 = expf(-0.5f * zq * zq);
                s_lev[k*32 + i + 16] = vp1;
            }
            if (slp == 0) {
                g_klat[fk*16 + i] = vy;
                g_klon[fk*16 + i] = vx;
                g_klev[fk*32 + i] = vp0;
                g_klev[fk*32 + i + 16] = vp1;
            }
            if (tid < 16) {
                const float r = expf(-1.f / (expf(lt_time[f*16 + tid]) + 1e-6f));
                s_r[tid] = r;
                if (slp == 0) g_r[f*16 + tid] = r;
            }
        }
        // Zero this producer's out slice (before the gate -> before any atomics)
        if (tid < 64) out[bid*64 + tid] = 0.f;
        __syncthreads();

        // Integrate 512 columns (2/thread) for all 16 k
        float wf[16];
        #pragma unroll
        for (int k = 0; k < 16; ++k) wf[k] = 0.f;
        const float4* q4 = (const float4*)qw;
        #pragma unroll
        for (int it = 0; it < 2; ++it) {
            const int col = slp*512 + it*256 + tid;
            const float4 q0 = q4[col*2];
            const float4 q1 = q4[col*2 + 1];
            const int p = col & 31, x = (col >> 5) & 15, y = col >> 9;
            #pragma unroll
            for (int k = 0; k < 16; ++k) {
                const float r = s_r[k];
                float s = q1.w;
                s = fmaf(s, r, q1.z); s = fmaf(s, r, q1.y); s = fmaf(s, r, q1.x);
                s = fmaf(s, r, q0.w); s = fmaf(s, r, q0.z); s = fmaf(s, r, q0.y);
                s = fmaf(s, r, q0.x);
                wf[k] = fmaf(s, s_lat[k*16 + y] * s_lon[k*16 + x] * s_lev[k*32 + p],
                             wf[k]);
            }
        }
        // Halving-transpose reduce 16 values over the warp, cross-warp via smem
        #pragma unroll
        for (int s = 0; s < 4; ++s) {
            const int stride = 1 << s;
            const int nh = 8 >> s;
            const bool hi = (lane >> s) & 1;
            #pragma unroll
            for (int i = 0; i < nh; ++i) {
                float send = hi ? wf[i] : wf[i + nh];
                float keep = hi ? wf[i + nh] : wf[i];
                wf[i] = keep + __shfl_xor_sync(0xffffffffu, send, stride);
            }
        }
        wf[0] += __shfl_xor_sync(0xffffffffu, wf[0], 16);
        if (lane < 16) s_ired[wid*16 + bitrev4(lane)] = wf[0];
        __syncthreads();
        if (tid < 16) {
            float s = 0.f;
            #pragma unroll
            for (int w8 = 0; w8 < 8; ++w8) s += s_ired[w8*16 + tid];
            g_ipart[(f*16 + tid)*16 + slp] = s;
        }
        __syncthreads();
        __threadfence();
        if (tid == 0) atomicAdd(&g_done, 1u);
    }

    // ---- Gate: wait until all 128 producers have published ----
    if (tid == 0) {
        while (*(volatile unsigned int*)&g_done < (unsigned)NPROD)
            __nanosleep(64);
    }
    __syncthreads();
    __threadfence();

    // ---- s_cl: klat*klon/(integ+1e-4) for this (f, sl) ----
    if (tid < 16) {
        const int fk = f*16 + tid;
        const float4* ip = (const float4*)&g_ipart[fk*16];
        float4 a = ip[0], b = ip[1], c = ip[2], d = ip[3];
        float integ = ((a.x + a.y) + (a.z + a.w)) + ((b.x + b.y) + (b.z + b.w))
                    + ((c.x + c.y) + (c.z + c.w)) + ((d.x + d.y) + (d.z + d.w));
        s_cl[tid] = g_klat[fk*16 + (sl >> 4)] * g_klon[fk*16 + (sl & 15)]
                    / (integ + 1e-4f);
    }
    __syncthreads();

    // ---- Build B (R12 layout): W[i][k] = qw_i * klev*r^t * clinv, tf32 ----
    {
        const int p = (tid >> 3) & 31, t = tid & 7;
        const float qwv = qw[sl*256 + tid];
        #pragma unroll
        for (int kq = 0; kq < 4; ++kq) {
            uint4 pk;
            uint32_t* pe = (uint32_t*)&pk;
            #pragma unroll
            for (int e = 0; e < 4; ++e) {
                const int k = kq*4 + e;
                const float r = g_r[f*16 + k];
                const float r2 = r*r, r4 = r2*r2;
                float rt = 1.f;
                if (t & 1) rt *= r;
                if (t & 2) rt *= r2;
                if (t & 4) rt *= r4;
                const float kl = g_klev[(f*16 + k)*NP + p];
                pe[e] = f2tf32(qwv * kl * rt * s_cl[k]);
            }
            *(uint4*)&Bs[tid*BS_STRIDE + kq*4] = pk;
        }
    }

    // ---- Mainloop (byte-identical to R12) ----
    float acc[2][4] = {};
    #pragma unroll
    for (int sub = 0; sub < 4; ++sub) {
        if (sub < 3) cp_wait<1>(); else cp_wait<0>();
        __syncthreads();

        const float* Ab = As + (sub & 1)*AS_U32;
        const float* ar0 = Ab + (mt*16 + g    )*AS_STRIDE;
        const float* ar8 = Ab + (mt*16 + g + 8)*AS_STRIDE;
        #pragma unroll
        for (int j = 0; j < 4; ++j) {
            const int icl = kh*32 + j*8;       // col within 64-col round
            const int icb = sub*64 + icl;      // row in Bs (0..255)
            const uint32_t a0 = f2tf32(ar0[icl + tg]);
            const uint32_t a1 = f2tf32(ar8[icl + tg]);
            const uint32_t a2 = f2tf32(ar0[icl + tg + 4]);
            const uint32_t a3 = f2tf32(ar8[icl + tg + 4]);
            const uint32_t b0 = Bs[(icb + tg    )*BS_STRIDE + g];
            const uint32_t b1 = Bs[(icb + tg + 4)*BS_STRIDE + g];
            const uint32_t c0 = Bs[(icb + tg    )*BS_STRIDE + g + 8];
            const uint32_t c1 = Bs[(icb + tg + 4)*BS_STRIDE + g + 8];
            mma_tf32(acc[0], a0, a1, a2, a3, b0, b1);
            mma_tf32(acc[1], a0, a1, a2, a3, c0, c1);
        }
        __syncthreads();   // buffer sub&1 fully consumed

        if (sub < 2) {
            const int col0 = (sub + 2)*64;
            #pragma unroll
            for (int it = 0; it < 4; ++it)
                cp16(&As[(sub & 1)*AS_U32 + (row0 + it*16)*AS_STRIDE + c4*4],
                     abase + (size_t)(row0 + it*16) * bstride + col0 + c4*4);
            cp_commit();
        }
    }

    // ---- Epilogue (R12): pair-reduce K-halves, atomicAdd into out ----
    if (kh == 1) {
        float* sp = s_par + mt*256;
        sp[(g    )*16 + tg*2    ] = acc[0][0];
        sp[(g    )*16 + tg*2 + 1] = acc[0][1];
        sp[(g + 8)*16 + tg*2    ] = acc[0][2];
        sp[(g + 8)*16 + tg*2 + 1] = acc[0][3];
        sp[(g    )*16 + 8 + tg*2    ] = acc[1][0];
        sp[(g    )*16 + 8 + tg*2 + 1] = acc[1][1];
        sp[(g + 8)*16 + 8 + tg*2    ] = acc[1][2];
        sp[(g + 8)*16 + 8 + tg*2 + 1] = acc[1][3];
    }
    __syncthreads();
    if (kh == 0) {
        const float* sp = s_par + mt*256;
        const int r0 = mt*16 + g, r1 = r0 + 8;
        float* o0 = out + (size_t)r0 * (NF*NK) + f*NK;
        float* o1 = out + (size_t)r1 * (NF*NK) + f*NK;
        atomicAdd(&o0[tg*2    ], acc[0][0] + sp[(g    )*16 + tg*2    ]);
        atomicAdd(&o0[tg*2 + 1], acc[0][1] + sp[(g    )*16 + tg*2 + 1]);
        atomicAdd(&o1[tg*2    ], acc[0][2] + sp[(g + 8)*16 + tg*2    ]);
        atomicAdd(&o1[tg*2 + 1], acc[0][3] + sp[(g + 8)*16 + tg*2 + 1]);
        atomicAdd(&o0[8 + tg*2    ], acc[1][0] + sp[(g    )*16 + 8 + tg*2    ]);
        atomicAdd(&o0[8 + tg*2 + 1], acc[1][1] + sp[(g    )*16 + 8 + tg*2 + 1]);
        atomicAdd(&o1[8 + tg*2    ], acc[1][2] + sp[(g + 8)*16 + 8 + tg*2    ]);
        atomicAdd(&o1[8 + tg*2 + 1], acc[1][3] + sp[(g + 8)*16 + 8 + tg*2 + 1]);
    }

    // ---- Completion ticket: last CTA resets counters for graph replay.
    // Safe: every CTA finished polling g_done before it increments g_fin,
    // so the reset can never race a poll.
    if (tid == 0) {
        if (atomicAdd(&g_fin, 1u) == (unsigned)(NCTA - 1)) {
            g_done = 0u;
            g_fin  = 0u;
        }
    }
}

// ---------------------------------------------------------------------------
// Launch. Inputs (metadata order): patch, quadweights, mu_lat, logsigma_lat,
// mu_lon, logsigma_lon, mu_lev, logsigma_lev, logtau_time.
// SINGLE kernel launch (producer gate replaces the prep kernel).
// ---------------------------------------------------------------------------
extern "C" void kernel_launch(void* const* d_in, const int* in_sizes, int n_in,
                              void* d_out, int out_size)
{
    (void)in_sizes; (void)n_in; (void)out_size;
    const float* patch  = (const float*)d_in[0];
    const float* qw     = (const float*)d_in[1];
    const float* mu_lat = (const float*)d_in[2];
    const float* ls_lat = (const float*)d_in[3];
    const float* mu_lon = (const float*)d_in[4];
    const float* ls_lon = (const float*)d_in[5];
    const float* mu_lev = (const float*)d_in[6];
    const float* ls_lev = (const float*)d_in[7];
    const float* lt     = (const float*)d_in[8];
    float* out = (float*)d_out;

    static bool attr_set = false;
    if (!attr_set) {
        cudaFuncSetAttribute(feat_kernel,
                             cudaFuncAttributeMaxDynamicSharedMemorySize, SMEM_TOTAL);
        attr_set = true;
    }

    feat_kernel<<<NCTA, 256, SMEM_TOTAL>>>(patch, qw, mu_lat, ls_lat,
                                           mu_lon, ls_lon, mu_lev, ls_lev,
                                           lt, out);
}

// round 17
// speedup vs baseline: 1.3932x; 1.0802x over previous
#include <cuda_runtime.h>
#include <cstdint>

// Problem constants
#define NF 8
#define NK 16
#define NY 16
#define NX 16
#define NP 32
#define NT 8
#define NB 64
#define VOL 65536          // elements per (b,f)

#define AS_STRIDE 68       // 64 cols + 4 pad (conflict-free writes / LDS.32)
#define BS_STRIDE 24       // 16 cols + 8 pad (conflict-free b-frag LDS.32)
#define AS_U32    (64*AS_STRIDE)                 // per buffer (fp32 words)
#define AS_BUFB   (AS_U32*4)                     // 17408 B per buffer
#define AS_BYTES  (3*AS_BUFB)                    // 52224 (triple buffer)
#define BS_BYTES  (256*BS_STRIDE*4)              // 24576
#define SMEM_TOTAL (AS_BYTES + BS_BYTES)         // 76800 -> 3 CTAs/SM

// Device globals (no allocation allowed)
__device__ float g_klat[NF*NK*NY];
__device__ float g_klon[NF*NK*NX];
__device__ float g_klev[NF*NK*NP];
__device__ float g_r[NF*NK];
__device__ float g_ipart[NF*NK*8];

__device__ __forceinline__ uint32_t f2tf32(float x) {
    uint32_t r; asm("cvt.rna.tf32.f32 %0, %1;" : "=r"(r) : "f"(x)); return r;
}
__device__ __forceinline__ void mma_tf32(float c[4], uint32_t a0, uint32_t a1,
                                         uint32_t a2, uint32_t a3,
                                         uint32_t b0, uint32_t b1) {
    asm volatile(
        "mma.sync.aligned.m16n8k8.row.col.f32.tf32.tf32.f32 "
        "{%0,%1,%2,%3},{%4,%5,%6,%7},{%8,%9},{%0,%1,%2,%3};"
        : "+f"(c[0]), "+f"(c[1]), "+f"(c[2]), "+f"(c[3])
        : "r"(a0), "r"(a1), "r"(a2), "r"(a3), "r"(b0), "r"(b1));
}

// cp.async helpers (16B, default .ca path)
__device__ __forceinline__ void cp16(void* dst_smem, const void* src) {
    uint32_t d = (uint32_t)__cvta_generic_to_shared(dst_smem);
    asm volatile("cp.async.ca.shared.global [%0],[%1],16;" :: "r"(d), "l"(src));
}
__device__ __forceinline__ void cp_commit() {
    asm volatile("cp.async.commit_group;");
}
template<int N> __device__ __forceinline__ void cp_wait() {
    asm volatile("cp.async.wait_group %0;" :: "n"(N));
}

// ---------------------------------------------------------------------------
// Prep (R12, unchanged): 8 sub-CTAs per (f,k) (1024 CTAs). 1D tables +
// geometric ratio r + non-atomic integration partials; zeroes out.
// ---------------------------------------------------------------------------
__global__ __launch_bounds__(256)
void prep_kernel(const float* __restrict__ qw,
                 const float* __restrict__ mu_lat, const float* __restrict__ ls_lat,
                 const float* __restrict__ mu_lon, const float* __restrict__ ls_lon,
                 const float* __restrict__ mu_lev, const float* __restrict__ ls_lev,
                 const float* __restrict__ lt_time,
                 float* __restrict__ out)
{
    const int bid = blockIdx.x;
    const int fk  = bid >> 3;
    const int sub = bid & 7;
    const int tid = threadIdx.x;
    __shared__ float s_lat[NY], s_lon[NX], s_lev[NP];
    __shared__ float s_part[8];

    if (tid < 8) out[bid*8 + tid] = 0.f;   // zero out (1024*8 = 8192)

    if (tid < NY) {
        float c = -1.f + 2.f * (float)tid / (float)(NY - 1);
        float z = (c - mu_lat[fk]) / expf(ls_lat[fk]);
        float v = expf(-0.5f * z * z);
        s_lat[tid] = v;
        if (sub == 0) g_klat[fk*NY + tid] = v;
    } else if (tid < 32) {
        int x = tid - 16;
        float c = -1.f + 2.f * (float)x / (float)(NX - 1);
        float z = (c - mu_lon[fk]) / expf(ls_lon[fk]);
        float v = expf(-0.5f * z * z);
        s_lon[x] = v;
        if (sub == 0) g_klon[fk*NX + x] = v;
    } else if (tid < 64) {
        int p = tid - 32;
        float c = -1.f + 2.f * (float)p / (float)(NP - 1);
        float z = (c - mu_lev[fk]) / expf(ls_lev[fk]);
        float v = expf(-0.5f * z * z);
        s_lev[p] = v;
        if (sub == 0) g_klev[fk*NP + p] = v;
    }
    float tau = expf(lt_time[fk]) + 1e-6f;
    float r = expf(-1.f / tau);
    if (sub == 0 && tid == 0) g_r[fk] = r;
    __syncthreads();

    const float4* q4 = (const float4*)qw;
    float local = 0.f;
    #pragma unroll
    for (int it = 0; it < 4; ++it) {
        int idx = sub*1024 + it*256 + tid;
        float4 q0 = q4[idx*2];
        float4 q1 = q4[idx*2 + 1];
        float s = q1.w;
        s = fmaf(s, r, q1.z); s = fmaf(s, r, q1.y); s = fmaf(s, r, q1.x);
        s = fmaf(s, r, q0.w); s = fmaf(s, r, q0.z); s = fmaf(s, r, q0.y);
        s = fmaf(s, r, q0.x);
        int p = idx & 31, x = (idx >> 5) & 15, y = idx >> 9;
        local += s * (s_lat[y] * s_lon[x] * s_lev[p]);
    }
    #pragma unroll
    for (int o = 16; o; o >>= 1) local += __shfl_xor_sync(0xffffffffu, local, o);
    if ((tid & 31) == 0) s_part[tid >> 5] = local;
    __syncthreads();
    if (tid == 0) {
        float s = 0.f;
        #pragma unroll
        for (int w = 0; w < 8; ++w) s += s_part[w];
        g_ipart[bid] = s;
    }
}

// ---------------------------------------------------------------------------
// Main GEMM kernel: grid = 2048 (f = bid&7, sl = bid>>3 = one yx slice).
// C[64,16] = patch[64, 256] x W[256, 16] (tf32 mma.sync m16n8k8).
// TRIPLE-buffered cp.async ring: stages 0-2 (48 KB/CTA) in flight before the
// first MMA; only stage 3 issued mid-loop. 5 barriers/CTA (vs 8 in R12).
// s_par (epilogue scratch) aliases As buffer 0 (dead after final barrier).
// Epilogue: pair-reduce K-halves via smem, atomicAdd into out.
// ---------------------------------------------------------------------------
__global__ __launch_bounds__(256, 3)
void feat_kernel(const float* __restrict__ patch, const float* __restrict__ qw,
                 float* __restrict__ out)
{
    extern __shared__ __align__(16) char dynsmem[];
    float*    As    = (float*)dynsmem;                  // [3][64][68] fp32
    uint32_t* Bs    = (uint32_t*)(dynsmem + AS_BYTES);  // [256][24] tf32
    float*    s_par = (float*)dynsmem;                  // alias As buf0
    __shared__ float s_cl[16];

    const int bid  = blockIdx.x;
    const int f    = bid & 7;
    const int sl   = bid >> 3;            // yx index 0..255
    const int tid  = threadIdx.x;
    const int lane = tid & 31, wid = tid >> 5;
    const int g = lane >> 2, tg = lane & 3;
    const int mt = wid & 3, kh = wid >> 2;

    const size_t bstride = (size_t)NF * VOL;
    const float* abase = patch + (size_t)f * VOL + (size_t)sl * 256;
    const int row0 = tid >> 4;            // rows row0, +16, +32, +48
    const int c4   = tid & 15;

    // Stages 0 and 1 issued at entry (independent of tables)
    #pragma unroll
    for (int it = 0; it < 4; ++it)
        cp16(&As[(row0 + it*16)*AS_STRIDE + c4*4],
             abase + (size_t)(row0 + it*16) * bstride + c4*4);
    cp_commit();
    #pragma unroll
    for (int it = 0; it < 4; ++it)
        cp16(&As[AS_U32 + (row0 + it*16)*AS_STRIDE + c4*4],
             abase + (size_t)(row0 + it*16) * bstride + 64 + c4*4);
    cp_commit();

    if (tid < 16) {
        const int fk = f*16 + tid;
        float integ = 0.f;
        #pragma unroll
        for (int i = 0; i < 8; ++i) integ += g_ipart[fk*8 + i];
        s_cl[tid] = g_klat[fk*NY + (sl >> 4)] * g_klon[fk*NX + (sl & 15)]
                    / (integ + 1e-4f);
    }
    __syncthreads();

    // Build B: W[i][k] = qw_i * klev*r^t * clinv, tf32
    {
        const int p = (tid >> 3) & 31, t = tid & 7;
        const float qwv = qw[sl*256 + tid];
        #pragma unroll
        for (int kq = 0; kq < 4; ++kq) {
            uint4 pk;
            uint32_t* pe = (uint32_t*)&pk;
            #pragma unroll
            for (int e = 0; e < 4; ++e) {
                const int k = kq*4 + e;
                const float r = g_r[f*16 + k];
                const float r2 = r*r, r4 = r2*r2;
                float rt = 1.f;
                if (t & 1) rt *= r;
                if (t & 2) rt *= r2;
                if (t & 4) rt *= r4;
                const float kl = g_klev[(f*16 + k)*NP + p];
                pe[e] = f2tf32(qwv * kl * rt * s_cl[k]);
            }
            *(uint4*)&Bs[tid*BS_STRIDE + kq*4] = pk;
        }
    }

    // Stage 2 into buffer 2
    #pragma unroll
    for (int it = 0; it < 4; ++it)
        cp16(&As[2*AS_U32 + (row0 + it*16)*AS_STRIDE + c4*4],
             abase + (size_t)(row0 + it*16) * bstride + 128 + c4*4);
    cp_commit();

    float acc[2][4] = {};

    // One MMA round on a given buffer for this warp (mt, kh)
    auto mma_round = [&](int bufi, int sub) {
        const float* Ab = As + bufi*AS_U32;
        const float* ar0 = Ab + (mt*16 + g    )*AS_STRIDE;
        const float* ar8 = Ab + (mt*16 + g + 8)*AS_STRIDE;
        #pragma unroll
        for (int j = 0; j < 4; ++j) {
            const int icl = kh*32 + j*8;       // col within 64-col round
            const int icb = sub*64 + icl;      // row in Bs (0..255)
            const uint32_t a0 = f2tf32(ar0[icl + tg]);
            const uint32_t a1 = f2tf32(ar8[icl + tg]);
            const uint32_t a2 = f2tf32(ar0[icl + tg + 4]);
            const uint32_t a3 = f2tf32(ar8[icl + tg + 4]);
            const uint32_t b0 = Bs[(icb + tg    )*BS_STRIDE + g];
            const uint32_t b1 = Bs[(icb + tg + 4)*BS_STRIDE + g];
            const uint32_t c0 = Bs[(icb + tg    )*BS_STRIDE + g + 8];
            const uint32_t c1 = Bs[(icb + tg + 4)*BS_STRIDE + g + 8];
            mma_tf32(acc[0], a0, a1, a2, a3, b0, b1);
            mma_tf32(acc[1], a0, a1, a2, a3, c0, c1);
        }
    };

    // sub 0: need group 0 done (3 issued -> wait <=2)
    cp_wait<2>();
    __syncthreads();
    mma_round(0, 0);
    __syncthreads();               // buffer 0 consumed by all warps
    // Stage 3 into buffer 0
    #pragma unroll
    for (int it = 0; it < 4; ++it)
        cp16(&As[(row0 + it*16)*AS_STRIDE + c4*4],
             abase + (size_t)(row0 + it*16) * bstride + 192 + c4*4);
    cp_commit();

    // sub 1: 4 issued, need group 1 -> wait <=2
    cp_wait<2>();
    __syncthreads();
    mma_round(1, 1);

    // sub 2: need group 2 -> wait <=1
    cp_wait<1>();
    __syncthreads();
    mma_round(2, 2);

    // sub 3: need group 3 -> wait <=0
    cp_wait<0>();
    __syncthreads();
    mma_round(0, 3);

    // Pair-reduce the two K-halves (s_par aliases As buf0 — dead now after
    // this barrier), then atomicAdd into out.
    __syncthreads();
    if (kh == 1) {
        float* sp = s_par + mt*256;
        sp[(g    )*16 + tg*2    ] = acc[0][0];
        sp[(g    )*16 + tg*2 + 1] = acc[0][1];
        sp[(g + 8)*16 + tg*2    ] = acc[0][2];
        sp[(g + 8)*16 + tg*2 + 1] = acc[0][3];
        sp[(g    )*16 + 8 + tg*2    ] = acc[1][0];
        sp[(g    )*16 + 8 + tg*2 + 1] = acc[1][1];
        sp[(g + 8)*16 + 8 + tg*2    ] = acc[1][2];
        sp[(g + 8)*16 + 8 + tg*2 + 1] = acc[1][3];
    }
    __syncthreads();
    if (kh == 0) {
        const float* sp = s_par + mt*256;
        const int r0 = mt*16 + g, r1 = r0 + 8;
        float* o0 = out + (size_t)r0 * (NF*NK) + f*NK;
        float* o1 = out + (size_t)r1 * (NF*NK) + f*NK;
        atomicAdd(&o0[tg*2    ], acc[0][0] + sp[(g    )*16 + tg*2    ]);
        atomicAdd(&o0[tg*2 + 1], acc[0][1] + sp[(g    )*16 + tg*2 + 1]);
        atomicAdd(&o1[tg*2    ], acc[0][2] + sp[(g + 8)*16 + tg*2    ]);
        atomicAdd(&o1[tg*2 + 1], acc[0][3] + sp[(g + 8)*16 + tg*2 + 1]);
        atomicAdd(&o0[8 + tg*2    ], acc[1][0] + sp[(g    )*16 + 8 + tg*2    ]);
        atomicAdd(&o0[8 + tg*2 + 1], acc[1][1] + sp[(g    )*16 + 8 + tg*2 + 1]);
        atomicAdd(&o1[8 + tg*2    ], acc[1][2] + sp[(g + 8)*16 + 8 + tg*2    ]);
        atomicAdd(&o1[8 + tg*2 + 1], acc[1][3] + sp[(g + 8)*16 + 8 + tg*2 + 1]);
    }
}

// ---------------------------------------------------------------------------
// Launch. Inputs (metadata order): patch, quadweights, mu_lat, logsigma_lat,
// mu_lon, logsigma_lon, mu_lev, logsigma_lev, logtau_time.
// ---------------------------------------------------------------------------
extern "C" void kernel_launch(void* const* d_in, const int* in_sizes, int n_in,
                              void* d_out, int out_size)
{
    (void)in_sizes; (void)n_in; (void)out_size;
    const float* patch  = (const float*)d_in[0];
    const float* qw     = (const float*)d_in[1];
    const float* mu_lat = (const float*)d_in[2];
    const float* ls_lat = (const float*)d_in[3];
    const float* mu_lon = (const float*)d_in[4];
    const float* ls_lon = (const float*)d_in[5];
    const float* mu_lev = (const float*)d_in[6];
    const float* ls_lev = (const float*)d_in[7];
    const float* lt     = (const float*)d_in[8];
    float* out = (float*)d_out;

    static bool attr_set = false;
    if (!attr_set) {
        cudaFuncSetAttribute(feat_kernel,
                             cudaFuncAttributeMaxDynamicSharedMemorySize, SMEM_TOTAL);
        attr_set = true;
    }

    prep_kernel<<<NF*NK*8, 256>>>(qw, mu_lat, ls_lat, mu_lon, ls_lon,
                                  mu_lev, ls_lev, lt, out);
    feat_kernel<<<2048, 256, SMEM_TOTAL>>>(patch, qw, out);
}